// round 9
// baseline (speedup 1.0000x reference)
#include <cuda_runtime.h>

#define NB      8
#define BATCH   65536
#define SEQ     54
#define DIM     6
#define EPS     1e-5f

#define THREADS 128
#define ELEMS   7            // batch elements per CTA
#define TPE     18           // threads per element (3 rows each: r, r+18, r+36)
#define ACTIVE  (ELEMS*TPE)  // 126

// ---------------- shared layout (floats) ----------------
#define S_EW 0        // embed_w  [6][8]            -> 48
#define S_EB 48       // embed_b  [8]               -> 56
#define S_FW 56       // fc1_w    [8][6][8]   (384) -> 440
#define S_FB 440      // fc1_b    [8][8]      (64)  -> 504
#define S_LG 504      // ln_g     [8][8]      (64)  -> 568
#define S_LB 568      // ln_b     [8][8]      (64)  -> 632
#define S_IW 632      // inproj_w [8][18][8] (1152) -> 1784
#define S_IB 1784     // inproj_b [8][3][8]  (192)  -> 1976  (q/k/v bias rows)
#define S_OW 1976     // out_w    [8][6][8]  (384)  -> 2360
#define S_OB 2360     // out_b    [8][8]     (64)   -> 2424
#define S_KV 2424     // 7 tiles of TSTRIDE; tile = kv-packed [54][12]
#define TSTRIDE 664   // 648 + 16 pad; stride%32==24 -> distinct bank groups per warp
#define S_TOTAL (S_KV + ELEMS * TSTRIDE)   // 7072 floats = 28288 B

typedef unsigned long long u64;

// ---- packed f32x2 primitives (Blackwell FFMA2: double-rate fp32) ----
__device__ __forceinline__ u64 pk2(float lo, float hi) {
    u64 r;
    asm("mov.b64 %0, {%1, %2};" : "=l"(r)
        : "r"(__float_as_uint(lo)), "r"(__float_as_uint(hi)));
    return r;
}
__device__ __forceinline__ void upk2(u64 p, float& lo, float& hi) {
    unsigned a, b;
    asm("mov.b64 {%0, %1}, %2;" : "=r"(a), "=r"(b) : "l"(p));
    lo = __uint_as_float(a); hi = __uint_as_float(b);
}
__device__ __forceinline__ u64 mul2(u64 a, u64 b) {
    u64 d; asm("mul.rn.f32x2 %0, %1, %2;" : "=l"(d) : "l"(a), "l"(b)); return d;
}
__device__ __forceinline__ u64 add2(u64 a, u64 b) {
    u64 d; asm("add.rn.f32x2 %0, %1, %2;" : "=l"(d) : "l"(a), "l"(b)); return d;
}
__device__ __forceinline__ u64 fma2(u64 a, u64 b, u64 c) {
    u64 d; asm("fma.rn.f32x2 %0, %1, %2, %3;" : "=l"(d) : "l"(a), "l"(b), "l"(c)); return d;
}
__device__ __forceinline__ float hadd2(u64 p) { float lo, hi; upk2(p, lo, hi); return lo + hi; }

// packed dot over 6 elements (3 pairs): 3 packed FMA + horizontal add
__device__ __forceinline__ float dot6p(const u64 w[3], const u64 h[3]) {
    u64 p = mul2(w[0], h[0]);
    p = fma2(w[1], h[1], p);
    p = fma2(w[2], h[2], p);
    return hadd2(p);
}

// load an 8-float-padded weight row (32B aligned) as 3 packed pairs (2 LDS)
__device__ __forceinline__ void ldw6p(const float* __restrict__ p, u64 w[3]) {
    ulonglong2 t = *(const ulonglong2*)p;          // (w0,w1),(w2,w3)
    w[0] = t.x; w[1] = t.y;
    w[2] = *(const u64*)(p + 4);                   // (w4,w5)
}

__device__ __forceinline__ void ldvec6(const float* __restrict__ p, float v[6]) {
    float4 a = *(const float4*)p;
    float2 b = *(const float2*)(p + 4);
    v[0]=a.x; v[1]=a.y; v[2]=a.z; v[3]=a.w; v[4]=b.x; v[5]=b.y;
}

__device__ __forceinline__ float ex2(float x) {
    float y;
    asm("ex2.approx.ftz.f32 %0, %1;" : "=f"(y) : "f"(x));
    return y;
}

__device__ __forceinline__ float elu(float t) {
    return t > 0.f ? t : (__expf(t) - 1.f);
}

__device__ __forceinline__ void ln_row(float z[6], const float g[6], const float b[6]) {
    float mu = (z[0]+z[1]+z[2]+z[3]+z[4]+z[5]) * (1.0f/6.0f);
    float var = 0.f;
    #pragma unroll
    for (int d = 0; d < 6; d++) { float t = z[d] - mu; var = fmaf(t, t, var); }
    float is = rsqrtf(var * (1.0f/6.0f) + EPS);
    #pragma unroll
    for (int d = 0; d < 6; d++) z[d] = (z[d] - mu) * is * g[d] + b[d];
}

__global__ __launch_bounds__(THREADS, 6)
void rubik_kernel(const float* __restrict__ x,
                  const float* __restrict__ ew, const float* __restrict__ eb,
                  const float* __restrict__ fw, const float* __restrict__ fb,
                  const float* __restrict__ lg, const float* __restrict__ lb,
                  const float* __restrict__ iw, const float* __restrict__ ib,
                  const float* __restrict__ ow, const float* __restrict__ ob,
                  const float* __restrict__ vw, const float* __restrict__ vb,
                  const float* __restrict__ pw, const float* __restrict__ pb,
                  float* __restrict__ out)
{
    __shared__ __align__(16) float s[S_TOTAL];
    const int tid = threadIdx.x;

    // ---- stage weights into padded shared layout ----
    for (int t = tid; t < 36;  t += THREADS) s[S_EW + (t/6)*8 + t%6] = ew[t];
    for (int t = tid; t < 6;   t += THREADS) s[S_EB + t] = eb[t];
    for (int t = tid; t < 288; t += THREADS) { int b = t/36; s[S_FW + b*48 + ((t/6)%6)*8 + t%6] = fw[t]; }
    for (int t = tid; t < 48;  t += THREADS) s[S_FB + (t/6)*8 + t%6] = fb[t];
    for (int t = tid; t < 48;  t += THREADS) s[S_LG + (t/6)*8 + t%6] = lg[t];
    for (int t = tid; t < 48;  t += THREADS) s[S_LB + (t/6)*8 + t%6] = lb[t];
    for (int t = tid; t < 864; t += THREADS) { int b = t/108; s[S_IW + b*144 + ((t/6)%18)*8 + t%6] = iw[t]; }
    for (int t = tid; t < 144; t += THREADS) { int b = t/18, j = t%18; s[S_IB + b*24 + (j/6)*8 + j%6] = ib[t]; }
    for (int t = tid; t < 288; t += THREADS) { int b = t/36; s[S_OW + b*48 + ((t/6)%6)*8 + t%6] = ow[t]; }
    for (int t = tid; t < 48;  t += THREADS) s[S_OB + (t/6)*8 + t%6] = ob[t];
    __syncthreads();

    // ---- mapping: 7 elems x 18 threads; each thread owns rows r, r+18, r+36 ----
    const bool act = tid < ACTIVE;
    const int  e   = tid / TPE;
    const int  r0  = tid % TPE, r1 = r0 + 18, r2 = r0 + 36;
    const int  bie = blockIdx.x * ELEMS + e;
    const bool valid = act && (bie < BATCH);
    float* tile = s + S_KV + e * TSTRIDE;

    // ---- load x rows + embed; h kept PACKED (hp*[3]) for the whole kernel ----
    u64 hp0[3], hp1[3], hp2[3];
    {
        float xr0[6], xr1[6], xr2[6];
        if (valid) {
            const float* p0 = x + (size_t)bie * (SEQ*DIM) + r0*DIM;
            const float* p1 = x + (size_t)bie * (SEQ*DIM) + r1*DIM;
            const float* p2 = x + (size_t)bie * (SEQ*DIM) + r2*DIM;
            float2 a, b, c;
            a = *(const float2*)(p0); b = *(const float2*)(p0+2); c = *(const float2*)(p0+4);
            xr0[0]=a.x; xr0[1]=a.y; xr0[2]=b.x; xr0[3]=b.y; xr0[4]=c.x; xr0[5]=c.y;
            a = *(const float2*)(p1); b = *(const float2*)(p1+2); c = *(const float2*)(p1+4);
            xr1[0]=a.x; xr1[1]=a.y; xr1[2]=b.x; xr1[3]=b.y; xr1[4]=c.x; xr1[5]=c.y;
            a = *(const float2*)(p2); b = *(const float2*)(p2+2); c = *(const float2*)(p2+4);
            xr2[0]=a.x; xr2[1]=a.y; xr2[2]=b.x; xr2[3]=b.y; xr2[4]=c.x; xr2[5]=c.y;
        } else {
            #pragma unroll
            for (int d = 0; d < 6; d++) { xr0[d]=0.f; xr1[d]=0.f; xr2[d]=0.f; }
        }
        u64 xp0[3], xp1[3], xp2[3];
        xp0[0]=pk2(xr0[0],xr0[1]); xp0[1]=pk2(xr0[2],xr0[3]); xp0[2]=pk2(xr0[4],xr0[5]);
        xp1[0]=pk2(xr1[0],xr1[1]); xp1[1]=pk2(xr1[2],xr1[3]); xp1[2]=pk2(xr1[4],xr1[5]);
        xp2[0]=pk2(xr2[0],xr2[1]); xp2[1]=pk2(xr2[2],xr2[3]); xp2[2]=pk2(xr2[4],xr2[5]);
        float ebv[6]; ldvec6(s + S_EB, ebv);
        #pragma unroll
        for (int jp = 0; jp < 3; jp++) {
            const int j = 2*jp;
            u64 wa[3], wb[3];
            ldw6p(s + S_EW + j*8,     wa);
            ldw6p(s + S_EW + (j+1)*8, wb);
            hp0[jp] = pk2(ebv[j] + dot6p(wa, xp0), ebv[j+1] + dot6p(wb, xp0));
            hp1[jp] = pk2(ebv[j] + dot6p(wa, xp1), ebv[j+1] + dot6p(wb, xp1));
            hp2[jp] = pk2(ebv[j] + dot6p(wa, xp2), ebv[j+1] + dot6p(wb, xp2));
        }
    }

    // ---- 8 transformer blocks ----
    for (int b = 0; b < NB; b++) {
        const float* fwb = s + S_FW + b*48;
        const float* iwb = s + S_IW + b*144;
        const float* owb = s + S_OW + b*48;

        __syncthreads();   // prior block's tile reads done before overwrite

        u64 qp0[3], qp1[3], qp2[3];
        if (act) {
            // fc1 + ELU (packed dots on packed h)
            float z0[6], z1[6], z2[6];
            {
                float bf[6]; ldvec6(s + S_FB + b*8, bf);
                #pragma unroll
                for (int j = 0; j < 6; j++) {
                    u64 w[3]; ldw6p(fwb + j*8, w);
                    z0[j] = elu(bf[j] + dot6p(w, hp0));
                    z1[j] = elu(bf[j] + dot6p(w, hp1));
                    z2[j] = elu(bf[j] + dot6p(w, hp2));
                }
            }
            // LayerNorm, then pack z (scalars die here)
            u64 zp0[3], zp1[3], zp2[3];
            {
                float g[6], bl[6];
                ldvec6(s + S_LG + b*8, g);
                ldvec6(s + S_LB + b*8, bl);
                ln_row(z0, g, bl); ln_row(z1, g, bl); ln_row(z2, g, bl);
                zp0[0]=pk2(z0[0],z0[1]); zp0[1]=pk2(z0[2],z0[3]); zp0[2]=pk2(z0[4],z0[5]);
                zp1[0]=pk2(z1[0],z1[1]); zp1[1]=pk2(z1[2],z1[3]); zp1[2]=pk2(z1[4],z1[5]);
                zp2[0]=pk2(z2[0],z2[1]); zp2[1]=pk2(z2[2],z2[3]); zp2[2]=pk2(z2[4],z2[5]);
            }
            // q projection (pre-scaled by log2e/sqrt(6) for EX2), packed directly
            {
                const float qs = 0.588978587229f;
                float bq[6]; ldvec6(s + S_IB + b*24, bq);
                #pragma unroll
                for (int jp = 0; jp < 3; jp++) {
                    const int j = 2*jp;
                    u64 wa[3], wb[3];
                    ldw6p(iwb + j*8,     wa);
                    ldw6p(iwb + (j+1)*8, wb);
                    qp0[jp] = pk2((bq[j] + dot6p(wa, zp0))*qs, (bq[j+1] + dot6p(wb, zp0))*qs);
                    qp1[jp] = pk2((bq[j] + dot6p(wa, zp1))*qs, (bq[j+1] + dot6p(wb, zp1))*qs);
                    qp2[jp] = pk2((bq[j] + dot6p(wa, zp2))*qs, (bq[j+1] + dot6p(wb, zp2))*qs);
                }
            }
            // k projection -> store immediately (4-group then 2-group)
            {
                float bk[6]; ldvec6(s + S_IB + b*24 + 8, bk);
                float a0[4], a1[4], a2[4];
                #pragma unroll
                for (int j = 0; j < 4; j++) {
                    u64 w[3]; ldw6p(iwb + (6+j)*8, w);
                    a0[j] = bk[j] + dot6p(w, zp0);
                    a1[j] = bk[j] + dot6p(w, zp1);
                    a2[j] = bk[j] + dot6p(w, zp2);
                }
                *(float4*)(tile + r0*12) = make_float4(a0[0],a0[1],a0[2],a0[3]);
                *(float4*)(tile + r1*12) = make_float4(a1[0],a1[1],a1[2],a1[3]);
                *(float4*)(tile + r2*12) = make_float4(a2[0],a2[1],a2[2],a2[3]);
                u64 w4[3], w5[3];
                ldw6p(iwb + 10*8, w4);
                ldw6p(iwb + 11*8, w5);
                *(float2*)(tile + r0*12 + 4) = make_float2(bk[4] + dot6p(w4, zp0), bk[5] + dot6p(w5, zp0));
                *(float2*)(tile + r1*12 + 4) = make_float2(bk[4] + dot6p(w4, zp1), bk[5] + dot6p(w5, zp1));
                *(float2*)(tile + r2*12 + 4) = make_float2(bk[4] + dot6p(w4, zp2), bk[5] + dot6p(w5, zp2));
            }
            // v projection -> store immediately (2-group then 4-group)
            {
                float bv[6]; ldvec6(s + S_IB + b*24 + 16, bv);
                u64 w0[3], w1[3];
                ldw6p(iwb + 12*8, w0);
                ldw6p(iwb + 13*8, w1);
                *(float2*)(tile + r0*12 + 6) = make_float2(bv[0] + dot6p(w0, zp0), bv[1] + dot6p(w1, zp0));
                *(float2*)(tile + r1*12 + 6) = make_float2(bv[0] + dot6p(w0, zp1), bv[1] + dot6p(w1, zp1));
                *(float2*)(tile + r2*12 + 6) = make_float2(bv[0] + dot6p(w0, zp2), bv[1] + dot6p(w1, zp2));
                float a0[4], a1[4], a2[4];
                #pragma unroll
                for (int j = 0; j < 4; j++) {
                    u64 w[3]; ldw6p(iwb + (14+j)*8, w);
                    a0[j] = bv[2+j] + dot6p(w, zp0);
                    a1[j] = bv[2+j] + dot6p(w, zp1);
                    a2[j] = bv[2+j] + dot6p(w, zp2);
                }
                *(float4*)(tile + r0*12 + 8) = make_float4(a0[0],a0[1],a0[2],a0[3]);
                *(float4*)(tile + r1*12 + 8) = make_float4(a1[0],a1[1],a1[2],a1[3]);
                *(float4*)(tile + r2*12 + 8) = make_float4(a2[0],a2[1],a2[2],a2[3]);
            }
        }
        __syncthreads();   // tiles complete

        if (act) {
            // online softmax-attention, fully packed f32x2.
            // tile row = [k0..k5, v0..v5]; 48B-aligned -> reinterpret as packed pairs.
            // No max-subtraction: LN bounds the scores, EX2 cannot overflow.
            float l0 = 0.f, l1 = 0.f, l2 = 0.f;
            u64 ap0[3], ap1[3], ap2[3];
            {
                u64 z = pk2(0.f, 0.f);
                ap0[0]=z; ap0[1]=z; ap0[2]=z;
                ap1[0]=z; ap1[1]=z; ap1[2]=z;
                ap2[0]=z; ap2[1]=z; ap2[2]=z;
            }
            #pragma unroll 3
            for (int kk = 0; kk < SEQ; kk++) {
                const ulonglong2 K = *(const ulonglong2*)(tile + kk*12);      // (k0k1)(k2k3)
                const ulonglong2 M = *(const ulonglong2*)(tile + kk*12 + 4);  // (k4k5)(v0v1)
                const ulonglong2 V = *(const ulonglong2*)(tile + kk*12 + 8);  // (v2v3)(v4v5)
                u64 p0 = mul2(qp0[0], K.x);
                u64 p1 = mul2(qp1[0], K.x);
                u64 p2 = mul2(qp2[0], K.x);
                p0 = fma2(qp0[1], K.y, p0); p1 = fma2(qp1[1], K.y, p1); p2 = fma2(qp2[1], K.y, p2);
                p0 = fma2(qp0[2], M.x, p0); p1 = fma2(qp1[2], M.x, p1); p2 = fma2(qp2[2], M.x, p2);
                float e0 = ex2(hadd2(p0));
                float e1 = ex2(hadd2(p1));
                float e2 = ex2(hadd2(p2));
                l0 += e0; l1 += e1; l2 += e2;
                u64 ep0 = pk2(e0, e0), ep1 = pk2(e1, e1), ep2 = pk2(e2, e2);
                ap0[0] = fma2(ep0, M.y, ap0[0]); ap1[0] = fma2(ep1, M.y, ap1[0]); ap2[0] = fma2(ep2, M.y, ap2[0]);
                ap0[1] = fma2(ep0, V.x, ap0[1]); ap1[1] = fma2(ep1, V.x, ap1[1]); ap2[1] = fma2(ep2, V.x, ap2[1]);
                ap0[2] = fma2(ep0, V.y, ap0[2]); ap1[2] = fma2(ep1, V.y, ap1[2]); ap2[2] = fma2(ep2, V.y, ap2[2]);
            }

            // normalize -> packed o, then out projection + ELU + packed residual add
            {
                float rl0 = __fdividef(1.f, l0);
                float rl1 = __fdividef(1.f, l1);
                float rl2 = __fdividef(1.f, l2);
                u64 rp0 = pk2(rl0, rl0), rp1 = pk2(rl1, rl1), rp2 = pk2(rl2, rl2);
                #pragma unroll
                for (int i = 0; i < 3; i++) {
                    ap0[i] = mul2(ap0[i], rp0);
                    ap1[i] = mul2(ap1[i], rp1);
                    ap2[i] = mul2(ap2[i], rp2);
                }
            }
            {
                float bo[6]; ldvec6(s + S_OB + b*8, bo);
                #pragma unroll
                for (int jp = 0; jp < 3; jp++) {
                    const int j = 2*jp;
                    u64 wa[3], wb[3];
                    ldw6p(owb + j*8,     wa);
                    ldw6p(owb + (j+1)*8, wb);
                    hp0[jp] = add2(hp0[jp], pk2(elu(bo[j] + dot6p(wa, ap0)), elu(bo[j+1] + dot6p(wb, ap0))));
                    hp1[jp] = add2(hp1[jp], pk2(elu(bo[j] + dot6p(wa, ap1)), elu(bo[j+1] + dot6p(wb, ap1))));
                    hp2[jp] = add2(hp2[jp], pk2(elu(bo[j] + dot6p(wa, ap2)), elu(bo[j+1] + dot6p(wb, ap2))));
                }
            }
        }
    }

    // ---- heads ----
    __syncthreads();   // final attention reads complete; tiles become f-buffers
    if (act) {
        float* fs = tile;
        float lo, hi;
        #pragma unroll
        for (int jp = 0; jp < 3; jp++) {
            upk2(hp0[jp], lo, hi); *(float2*)(fs + r0*6 + 2*jp) = make_float2(lo, hi);
            upk2(hp1[jp], lo, hi); *(float2*)(fs + r1*6 + 2*jp) = make_float2(lo, hi);
            upk2(hp2[jp], lo, hi); *(float2*)(fs + r2*6 + 2*jp) = make_float2(lo, hi);
        }
    }
    __syncthreads();

    const int warp = tid >> 5, lane = tid & 31;
    for (int ee = warp; ee < ELEMS; ee += 4) {
        const int bi = blockIdx.x * ELEMS + ee;
        if (bi >= BATCH) break;
        const float* fs = s + S_KV + ee * TSTRIDE;

        float av = 0.f;
        float ap[12] = {0,0,0,0,0,0,0,0,0,0,0,0};
        for (int i = lane; i < SEQ*DIM; i += 32) {
            float fv = fs[i];
            av = fmaf(fv, __ldg(vw + i), av);
            #pragma unroll
            for (int j = 0; j < 12; j++) ap[j] = fmaf(fv, __ldg(pw + j*(SEQ*DIM) + i), ap[j]);
        }
        #pragma unroll
        for (int off = 16; off > 0; off >>= 1) {
            av += __shfl_xor_sync(0xffffffffu, av, off);
            #pragma unroll
            for (int j = 0; j < 12; j++) ap[j] += __shfl_xor_sync(0xffffffffu, ap[j], off);
        }
        av += __ldg(vb);
        #pragma unroll
        for (int j = 0; j < 12; j++) ap[j] += __ldg(pb + j);

        float m = ap[0];
        #pragma unroll
        for (int j = 1; j < 12; j++) m = fmaxf(m, ap[j]);
        float sum = 0.f;
        #pragma unroll
        for (int j = 0; j < 12; j++) sum += __expf(ap[j] - m);
        float rs = __fdividef(1.f, sum);

        if (lane == 0) out[bi] = av;
        #pragma unroll
        for (int j = 0; j < 12; j++) {
            if (lane == j) out[BATCH + (size_t)bi*12 + j] = __expf(ap[j] - m) * rs;
        }
    }
}

extern "C" void kernel_launch(void* const* d_in, const int* in_sizes, int n_in,
                              void* d_out, int out_size)
{
    (void)in_sizes; (void)n_in; (void)out_size;
    const float* x  = (const float*)d_in[0];
    const float* ew = (const float*)d_in[1];
    const float* eb = (const float*)d_in[2];
    const float* fw = (const float*)d_in[3];
    const float* fb = (const float*)d_in[4];
    const float* lg = (const float*)d_in[5];
    const float* lb = (const float*)d_in[6];
    const float* iw = (const float*)d_in[7];
    const float* ib = (const float*)d_in[8];
    const float* ow = (const float*)d_in[9];
    const float* ob = (const float*)d_in[10];
    const float* vw = (const float*)d_in[11];
    const float* vb = (const float*)d_in[12];
    const float* pw = (const float*)d_in[13];
    const float* pb = (const float*)d_in[14];
    float* out = (float*)d_out;

    const int grid = (BATCH + ELEMS - 1) / ELEMS;   // 9363
    rubik_kernel<<<grid, THREADS>>>(x, ew, eb, fw, fb, lg, lb,
                                    iw, ib, ow, ob, vw, vb, pw, pb, out);
}